// round 9
// baseline (speedup 1.0000x reference)
#include <cuda_runtime.h>
#include <math.h>
#include <stdint.h>

#define DIM   1024
#define BT    2
#define NT    2048
#define HEADS 16
#define HD    64
#define MLPD  4096
#define ROWS  (BT*NT)

// ---------------------------------------------------------------------------
// Scratch (static device globals)
// ---------------------------------------------------------------------------
__device__ float g_mod [BT*6*DIM];
__device__ float g_xn  [ROWS*DIM];
__device__ float g_q   [ROWS*DIM];
__device__ float g_k   [ROWS*DIM];
__device__ float g_v   [ROWS*DIM];
__device__ float g_attn[ROWS*DIM];
__device__ float g_h   [(size_t)ROWS*MLPD];
// tf32-rounded AND TRANSPOSED weights: Wq,Wk,Wv,Wo (1M each), W1 (4M), W2 (4M)
__device__ float g_wt  [12*1024*1024];

// ---------------------------------------------------------------------------
// PTX helpers
// ---------------------------------------------------------------------------
__device__ __forceinline__ uint32_t smaddr(const void* p){
    return (uint32_t)__cvta_generic_to_shared(p);
}
__device__ __forceinline__ void cp16(uint32_t d, const void* s){
    asm volatile("cp.async.cg.shared.global [%0], [%1], 16;\n" :: "r"(d), "l"(s));
}
__device__ __forceinline__ void cp_commit(){
    asm volatile("cp.async.commit_group;\n" ::);
}
__device__ __forceinline__ void cp_wait1(){
    asm volatile("cp.async.wait_group 1;\n" ::);
}
__device__ __forceinline__ float to_tf32(float x){
    float r;
    asm volatile("cvt.rna.tf32.f32 %0, %1;\n" : "=f"(r) : "f"(x));
    return r;
}
__device__ __forceinline__ void mma16n8k8(float* c, const float* a, const float* b){
    asm volatile(
        "mma.sync.aligned.m16n8k8.row.col.f32.tf32.tf32.f32 "
        "{%0,%1,%2,%3}, {%4,%5,%6,%7}, {%8,%9}, {%0,%1,%2,%3};\n"
        : "+f"(c[0]), "+f"(c[1]), "+f"(c[2]), "+f"(c[3])
        : "r"(__float_as_uint(a[0])), "r"(__float_as_uint(a[1])),
          "r"(__float_as_uint(a[2])), "r"(__float_as_uint(a[3])),
          "r"(__float_as_uint(b[0])), "r"(__float_as_uint(b[1])));
}

// ---------------------------------------------------------------------------
// 0) Round to tf32 AND transpose: in[K][N] -> out[N][K]
// ---------------------------------------------------------------------------
__global__ void __launch_bounds__(256) round_transpose_kernel(
    const float* __restrict__ in, float* __restrict__ out, int K, int N)
{
    __shared__ float t[32][33];
    int kb = blockIdx.y*32, nb = blockIdx.x*32;
    int tx = threadIdx.x & 31, ty = threadIdx.x >> 5;   // ty 0..7
    #pragma unroll
    for (int j = 0; j < 32; j += 8)
        t[ty+j][tx] = to_tf32(in[(size_t)(kb+ty+j)*N + nb + tx]);
    __syncthreads();
    #pragma unroll
    for (int j = 0; j < 32; j += 8)
        out[(size_t)(nb+ty+j)*K + kb + tx] = t[tx][ty+j];
}

// ---------------------------------------------------------------------------
// 1) mod = silu(t_emb) @ ada_W + ada_b
// ---------------------------------------------------------------------------
__global__ void __launch_bounds__(256) silu_mod_kernel(
    const float* __restrict__ t_emb, const float* __restrict__ adaW,
    const float* __restrict__ adab, float* __restrict__ mod)
{
    __shared__ float st[DIM];
    int b = blockIdx.y;
    int j = blockIdx.x * 256 + threadIdx.x;
    for (int i = threadIdx.x; i < DIM; i += 256) {
        float t = t_emb[b*DIM + i];
        st[i] = t / (1.f + __expf(-t));
    }
    __syncthreads();
    float acc = 0.f;
    #pragma unroll 4
    for (int kk = 0; kk < DIM; kk++)
        acc += st[kk] * adaW[(size_t)kk*6*DIM + j];
    mod[b*6*DIM + j] = acc + adab[j];
}

// ---------------------------------------------------------------------------
// 2) LN + adaLN modulation; output tf32-rounded
// ---------------------------------------------------------------------------
__global__ void __launch_bounds__(256) ln_mod_kernel(
    const float* __restrict__ x, float* __restrict__ out,
    const float* __restrict__ g, const float* __restrict__ bb,
    const float* __restrict__ mod, int shift_chunk, int scale_chunk)
{
    int row = blockIdx.x;
    int b   = row >> 11;
    int tid = threadIdx.x;
    const float* xr = x + (size_t)row*DIM;
    float4 xv = *(const float4*)(xr + tid*4);
    float s  = xv.x + xv.y + xv.z + xv.w;
    float s2 = xv.x*xv.x + xv.y*xv.y + xv.z*xv.z + xv.w*xv.w;
    #pragma unroll
    for (int o = 16; o > 0; o >>= 1) {
        s  += __shfl_xor_sync(0xffffffffu, s,  o);
        s2 += __shfl_xor_sync(0xffffffffu, s2, o);
    }
    __shared__ float ws[8], ws2[8];
    __shared__ float smu, srstd;
    int wid = tid >> 5;
    if ((tid & 31) == 0) { ws[wid] = s; ws2[wid] = s2; }
    __syncthreads();
    if (tid == 0) {
        float S = 0.f, S2 = 0.f;
        #pragma unroll
        for (int i = 0; i < 8; i++) { S += ws[i]; S2 += ws2[i]; }
        float mu  = S  * (1.f/DIM);
        float var = S2 * (1.f/DIM) - mu*mu;
        smu = mu; srstd = rsqrtf(var + 1e-5f);
    }
    __syncthreads();
    float mu = smu, rstd = srstd;
    int c = tid*4;
    const float* mb = mod + b*6*DIM;
    float4 gv = *(const float4*)(g  + c);
    float4 bv = *(const float4*)(bb + c);
    float4 sc = *(const float4*)(mb + scale_chunk*DIM + c);
    float4 sh = *(const float4*)(mb + shift_chunk*DIM + c);
    float4 y;
    y.x = to_tf32(((xv.x-mu)*rstd*gv.x + bv.x)*(1.f+sc.x) + sh.x);
    y.y = to_tf32(((xv.y-mu)*rstd*gv.y + bv.y)*(1.f+sc.y) + sh.y);
    y.z = to_tf32(((xv.z-mu)*rstd*gv.z + bv.z)*(1.f+sc.z) + sh.z);
    y.w = to_tf32(((xv.w-mu)*rstd*gv.w + bv.w)*(1.f+sc.w) + sh.w);
    *(float4*)(out + (size_t)row*DIM + c) = y;
}

// ---------------------------------------------------------------------------
// GEMM: Out(M,Nc) = A(M,K) @ W(K,Nc) with W given TRANSPOSED (Wt[Nc][K]).
//   BM=BN=128, BK=32, 8 warps (4M x 2N), warp 32x64.
//   k-slot permutation sigma(t)=2t, sigma(t+4)=2t+1 applied to BOTH operands
//   -> all fragment loads are contiguous float2 (LDS.64).
//   Smem rows padded to 40 floats -> conflict-free half-warp pattern 8g+2t.
// ---------------------------------------------------------------------------
#define G_ABUF 5120            // 128*40 floats
#define G_BBUF 5120            // 128*40 floats
#define G_BUF  (G_ABUF + G_BBUF)
#define G_SMEM_BYTES (2*G_BUF*4)

// EPI: 1 = exact GELU (rounded store), 2 = res + gate*acc (raw store)
template<int EPI>
__global__ void __launch_bounds__(256, 2) gemm_tc(
    const float* __restrict__ A, const float* __restrict__ Wt,
    float* __restrict__ Out, int M, int Nc, int K,
    const float* __restrict__ gate, const float* __restrict__ res)
{
    extern __shared__ float sm[];
    const int tid  = threadIdx.x;
    const int lane = tid & 31, warp = tid >> 5;
    const int grp  = lane >> 2, tig = lane & 3;
    const int wm   = warp & 3,  wn  = warp >> 2;
    const int m0   = blockIdx.y * 128, n0 = blockIdx.x * 128;
    const uint32_t smb = smaddr(sm);
    const int nk = K >> 5;

    float acc[2][8][4];
    #pragma unroll
    for (int i = 0; i < 2; i++)
        #pragma unroll
        for (int j = 0; j < 8; j++)
            #pragma unroll
            for (int t = 0; t < 4; t++) acc[i][j][t] = 0.f;

    auto prefetch = [&](int kc, int bufi){
        int off = bufi * G_BUF;
        #pragma unroll
        for (int i = 0; i < 4; i++) {
            int idx = tid + i*256;
            int r = idx >> 3, c4 = (idx & 7) * 4;
            cp16(smb + (uint32_t)(off + r*40 + c4)*4u,
                 A + (size_t)(m0 + r)*K + kc*32 + c4);
        }
        #pragma unroll
        for (int i = 0; i < 4; i++) {
            int idx = tid + i*256;
            int n = idx >> 3, c4 = (idx & 7) * 4;
            cp16(smb + (uint32_t)(off + G_ABUF + n*40 + c4)*4u,
                 Wt + (size_t)(n0 + n)*K + kc*32 + c4);
        }
    };

    prefetch(0, 0); cp_commit();
    int buf = 0;
    for (int kc = 0; kc < nk; kc++) {
        if (kc + 1 < nk) prefetch(kc + 1, buf ^ 1);
        cp_commit();
        cp_wait1();
        __syncthreads();
        const float* As = sm + buf*G_BUF;
        const float* Bs = As + G_ABUF;
        #pragma unroll
        for (int kk = 0; kk < 32; kk += 8) {
            float af[2][4], bf[8][2];
            #pragma unroll
            for (int ma = 0; ma < 2; ma++) {
                int r = wm*32 + ma*16 + grp;
                float2 p0 = *(const float2*)&As[r    *40 + kk + 2*tig];
                float2 p1 = *(const float2*)&As[(r+8)*40 + kk + 2*tig];
                af[ma][0] = p0.x; af[ma][1] = p1.x;
                af[ma][2] = p0.y; af[ma][3] = p1.y;
            }
            #pragma unroll
            for (int nb = 0; nb < 8; nb++) {
                int c = wn*64 + nb*8 + grp;
                float2 q = *(const float2*)&Bs[c*40 + kk + 2*tig];
                bf[nb][0] = q.x; bf[nb][1] = q.y;
            }
            #pragma unroll
            for (int ma = 0; ma < 2; ma++)
                #pragma unroll
                for (int nb = 0; nb < 8; nb++)
                    mma16n8k8(acc[ma][nb], af[ma], bf[nb]);
        }
        __syncthreads();
        buf ^= 1;
    }

    #pragma unroll
    for (int ma = 0; ma < 2; ma++) {
        int r0 = m0 + wm*32 + ma*16 + grp;
        #pragma unroll
        for (int nb = 0; nb < 8; nb++) {
            int c = n0 + wn*64 + nb*8 + 2*tig;
            float o0 = acc[ma][nb][0], o1 = acc[ma][nb][1];
            float o2 = acc[ma][nb][2], o3 = acc[ma][nb][3];
            if (EPI == 1) {
                o0 = to_tf32(0.5f*o0*(1.f + erff(o0*0.70710678f)));
                o1 = to_tf32(0.5f*o1*(1.f + erff(o1*0.70710678f)));
                o2 = to_tf32(0.5f*o2*(1.f + erff(o2*0.70710678f)));
                o3 = to_tf32(0.5f*o3*(1.f + erff(o3*0.70710678f)));
            } else if (EPI == 2) {
                int bi = r0 >> 11;
                float2 g2 = *(const float2*)(gate + bi*6*DIM + c);
                float2 ra = *(const float2*)(res + (size_t)r0    *Nc + c);
                float2 rb = *(const float2*)(res + (size_t)(r0+8)*Nc + c);
                o0 = ra.x + g2.x*o0; o1 = ra.y + g2.y*o1;
                o2 = rb.x + g2.x*o2; o3 = rb.y + g2.y*o3;
            }
            *(float2*)(Out + (size_t)r0    *Nc + c) = make_float2(o0, o1);
            *(float2*)(Out + (size_t)(r0+8)*Nc + c) = make_float2(o2, o3);
        }
    }
}

// Fused QKV (weights transposed): grid.x = 24, sel = bx>>3
__global__ void __launch_bounds__(256, 2) gemm_qkv(
    const float* __restrict__ A,
    const float* __restrict__ Wq, const float* __restrict__ Wk,
    const float* __restrict__ Wv,
    float* __restrict__ oq, float* __restrict__ ok, float* __restrict__ ov)
{
    extern __shared__ float sm[];
    const int tid  = threadIdx.x;
    const int lane = tid & 31, warp = tid >> 5;
    const int grp  = lane >> 2, tig = lane & 3;
    const int wm   = warp & 3,  wn  = warp >> 2;
    const int sel  = blockIdx.x >> 3;
    const int m0   = blockIdx.y * 128, n0 = (blockIdx.x & 7) * 128;
    const float* Wt = (sel == 0) ? Wq : (sel == 1) ? Wk : Wv;
    float* Out      = (sel == 0) ? oq : (sel == 1) ? ok : ov;
    const uint32_t smb = smaddr(sm);

    float acc[2][8][4];
    #pragma unroll
    for (int i = 0; i < 2; i++)
        #pragma unroll
        for (int j = 0; j < 8; j++)
            #pragma unroll
            for (int t = 0; t < 4; t++) acc[i][j][t] = 0.f;

    auto prefetch = [&](int kc, int bufi){
        int off = bufi * G_BUF;
        #pragma unroll
        for (int i = 0; i < 4; i++) {
            int idx = tid + i*256;
            int r = idx >> 3, c4 = (idx & 7) * 4;
            cp16(smb + (uint32_t)(off + r*40 + c4)*4u,
                 A + (size_t)(m0 + r)*DIM + kc*32 + c4);
        }
        #pragma unroll
        for (int i = 0; i < 4; i++) {
            int idx = tid + i*256;
            int n = idx >> 3, c4 = (idx & 7) * 4;
            cp16(smb + (uint32_t)(off + G_ABUF + n*40 + c4)*4u,
                 Wt + (size_t)(n0 + n)*DIM + kc*32 + c4);
        }
    };

    prefetch(0, 0); cp_commit();
    int buf = 0;
    for (int kc = 0; kc < DIM/32; kc++) {
        if (kc + 1 < DIM/32) prefetch(kc + 1, buf ^ 1);
        cp_commit();
        cp_wait1();
        __syncthreads();
        const float* As = sm + buf*G_BUF;
        const float* Bs = As + G_ABUF;
        #pragma unroll
        for (int kk = 0; kk < 32; kk += 8) {
            float af[2][4], bf[8][2];
            #pragma unroll
            for (int ma = 0; ma < 2; ma++) {
                int r = wm*32 + ma*16 + grp;
                float2 p0 = *(const float2*)&As[r    *40 + kk + 2*tig];
                float2 p1 = *(const float2*)&As[(r+8)*40 + kk + 2*tig];
                af[ma][0] = p0.x; af[ma][1] = p1.x;
                af[ma][2] = p0.y; af[ma][3] = p1.y;
            }
            #pragma unroll
            for (int nb = 0; nb < 8; nb++) {
                int c = wn*64 + nb*8 + grp;
                float2 q = *(const float2*)&Bs[c*40 + kk + 2*tig];
                bf[nb][0] = q.x; bf[nb][1] = q.y;
            }
            #pragma unroll
            for (int ma = 0; ma < 2; ma++)
                #pragma unroll
                for (int nb = 0; nb < 8; nb++)
                    mma16n8k8(acc[ma][nb], af[ma], bf[nb]);
        }
        __syncthreads();
        buf ^= 1;
    }

    #pragma unroll
    for (int ma = 0; ma < 2; ma++) {
        int r0 = m0 + wm*32 + ma*16 + grp;
        #pragma unroll
        for (int nb = 0; nb < 8; nb++) {
            int c = n0 + wn*64 + nb*8 + 2*tig;
            float o0 = to_tf32(acc[ma][nb][0]);
            float o1 = to_tf32(acc[ma][nb][1]);
            float o2 = to_tf32(acc[ma][nb][2]);
            float o3 = to_tf32(acc[ma][nb][3]);
            *(float2*)(Out + (size_t)r0    *DIM + c) = make_float2(o0, o1);
            *(float2*)(Out + (size_t)(r0+8)*DIM + c) = make_float2(o2, o3);
        }
    }
}

// ---------------------------------------------------------------------------
// 4) RoPE (outputs tf32-rounded)
// ---------------------------------------------------------------------------
__global__ void __launch_bounds__(256) rope_kernel(float* __restrict__ q,
                                                   float* __restrict__ k)
{
    int idx = blockIdx.x*256 + threadIdx.x;
    int n = (idx >> 4) & (NT-1);
    float cs[32], sn[32];
    #pragma unroll
    for (int j = 0; j < 32; j++) {
        float invf = expf((float)j * -0.2878231366f);
        float ang  = (float)n * invf;
        sincosf(ang, &sn[j], &cs[j]);
    }
    float* ptrs[2]; ptrs[0] = q + (size_t)idx*64; ptrs[1] = k + (size_t)idx*64;
    #pragma unroll
    for (int tpi = 0; tpi < 2; tpi++) {
        float* p = ptrs[tpi];
        float buf[64];
        #pragma unroll
        for (int u = 0; u < 16; u++) {
            float4 t = *(const float4*)(p + u*4);
            buf[u*4+0] = t.x; buf[u*4+1] = t.y; buf[u*4+2] = t.z; buf[u*4+3] = t.w;
        }
        #pragma unroll
        for (int t = 0; t < 8; t++) {
            float4 lo, hi;
            lo.x = to_tf32(buf[4*t+0]*cs[4*t+0] - buf[8*t+1]*sn[4*t+0]);
            lo.y = to_tf32(buf[4*t+1]*cs[4*t+1] - buf[8*t+3]*sn[4*t+1]);
            lo.z = to_tf32(buf[4*t+2]*cs[4*t+2] - buf[8*t+5]*sn[4*t+2]);
            lo.w = to_tf32(buf[4*t+3]*cs[4*t+3] - buf[8*t+7]*sn[4*t+3]);
            hi.x = to_tf32(buf[32+4*t+0]*cs[4*t+0] + buf[8*t+0]*sn[4*t+0]);
            hi.y = to_tf32(buf[32+4*t+1]*cs[4*t+1] + buf[8*t+2]*sn[4*t+1]);
            hi.z = to_tf32(buf[32+4*t+2]*cs[4*t+2] + buf[8*t+4]*sn[4*t+2]);
            hi.w = to_tf32(buf[32+4*t+3]*cs[4*t+3] + buf[8*t+6]*sn[4*t+3]);
            *(float4*)(p + 4*t)      = lo;
            *(float4*)(p + 32 + 4*t) = hi;
        }
    }
}

// ---------------------------------------------------------------------------
// 5) Flash attention (tf32 mma, sigma k-pairing on Q/K/P; V strided,
//    pads: Q/K/P rows 72, V rows 76 (conflict-free under sigma indexing))
// ---------------------------------------------------------------------------
#define F_QS 0
#define F_KS (64*72)
#define F_PS (2*64*72)
#define F_VS (3*64*72)
#define F_SMEM_BYTES ((3*64*72 + 64*76)*4)

__global__ void __launch_bounds__(128) flash_tc(
    const float* __restrict__ q, const float* __restrict__ k,
    const float* __restrict__ v, float* __restrict__ o)
{
    extern __shared__ float sm[];
    float* Qs = sm + F_QS;
    float* Ks = sm + F_KS;
    float* Ps = sm + F_PS;
    float* Vs = sm + F_VS;

    const int qt = blockIdx.x, bh = blockIdx.y;
    const int b = bh >> 4, h = bh & 15;
    const int tid = threadIdx.x;
    const int lane = tid & 31, warp = tid >> 5;
    const int grp = lane >> 2, tig = lane & 3;
    const int wrow = warp * 16;
    const float* qb = q + (size_t)b*NT*DIM + h*HD;
    const float* kb = k + (size_t)b*NT*DIM + h*HD;
    const float* vb = v + (size_t)b*NT*DIM + h*HD;

    #pragma unroll
    for (int i = 0; i < 8; i++) {
        int idx = tid + i*128;
        int r = idx >> 4, c4 = (idx & 15) * 4;
        float4 t = *(const float4*)(qb + (size_t)(qt*64 + r)*DIM + c4);
        t.x *= 0.125f; t.y *= 0.125f; t.z *= 0.125f; t.w *= 0.125f;
        *(float4*)(Qs + r*72 + c4) = t;
    }

    float O[8][4];
    #pragma unroll
    for (int i = 0; i < 8; i++)
        #pragma unroll
        for (int j = 0; j < 4; j++) O[i][j] = 0.f;
    float m0 = -1e30f, m1 = -1e30f, l0 = 0.f, l1 = 0.f;

    for (int kt = 0; kt < NT/64; kt++) {
        __syncthreads();
        #pragma unroll
        for (int i = 0; i < 8; i++) {
            int idx = tid + i*128;
            int r = idx >> 4, c4 = (idx & 15) * 4;
            float4 kv = *(const float4*)(kb + (size_t)(kt*64 + r)*DIM + c4);
            *(float4*)(Ks + r*72 + c4) = kv;
            float4 vv = *(const float4*)(vb + (size_t)(kt*64 + r)*DIM + c4);
            *(float4*)(Vs + r*76 + c4) = vv;
        }
        __syncthreads();

        // S = Q @ K^T  (sigma pairing -> float2 loads)
        float s[8][4];
        #pragma unroll
        for (int i = 0; i < 8; i++)
            #pragma unroll
            for (int j = 0; j < 4; j++) s[i][j] = 0.f;
        #pragma unroll
        for (int kk = 0; kk < 64; kk += 8) {
            float af[4];
            float2 p0 = *(const float2*)&Qs[(wrow+grp  )*72 + kk + 2*tig];
            float2 p1 = *(const float2*)&Qs[(wrow+grp+8)*72 + kk + 2*tig];
            af[0] = p0.x; af[1] = p1.x; af[2] = p0.y; af[3] = p1.y;
            #pragma unroll
            for (int nb = 0; nb < 8; nb++) {
                float bf[2];
                float2 qk = *(const float2*)&Ks[(nb*8+grp)*72 + kk + 2*tig];
                bf[0] = qk.x; bf[1] = qk.y;
                mma16n8k8(s[nb], af, bf);
            }
        }

        float mx0 = -1e30f, mx1 = -1e30f;
        #pragma unroll
        for (int nb = 0; nb < 8; nb++) {
            mx0 = fmaxf(mx0, fmaxf(s[nb][0], s[nb][1]));
            mx1 = fmaxf(mx1, fmaxf(s[nb][2], s[nb][3]));
        }
        mx0 = fmaxf(mx0, __shfl_xor_sync(0xffffffffu, mx0, 1));
        mx0 = fmaxf(mx0, __shfl_xor_sync(0xffffffffu, mx0, 2));
        mx1 = fmaxf(mx1, __shfl_xor_sync(0xffffffffu, mx1, 1));
        mx1 = fmaxf(mx1, __shfl_xor_sync(0xffffffffu, mx1, 2));
        float nm0 = fmaxf(m0, mx0), nm1 = fmaxf(m1, mx1);
        float a0 = __expf(m0 - nm0), a1 = __expf(m1 - nm1);
        float rs0 = 0.f, rs1 = 0.f;
        #pragma unroll
        for (int nb = 0; nb < 8; nb++) {
            float p0 = to_tf32(__expf(s[nb][0] - nm0));
            float p1 = to_tf32(__expf(s[nb][1] - nm0));
            float p2 = to_tf32(__expf(s[nb][2] - nm1));
            float p3 = to_tf32(__expf(s[nb][3] - nm1));
            rs0 += p0 + p1; rs1 += p2 + p3;
            *(float2*)(Ps + (wrow+grp  )*72 + nb*8 + 2*tig) = make_float2(p0, p1);
            *(float2*)(Ps + (wrow+grp+8)*72 + nb*8 + 2*tig) = make_float2(p2, p3);
            O[nb][0] *= a0; O[nb][1] *= a0;
            O[nb][2] *= a1; O[nb][3] *= a1;
        }
        rs0 += __shfl_xor_sync(0xffffffffu, rs0, 1);
        rs0 += __shfl_xor_sync(0xffffffffu, rs0, 2);
        rs1 += __shfl_xor_sync(0xffffffffu, rs1, 1);
        rs1 += __shfl_xor_sync(0xffffffffu, rs1, 2);
        l0 = l0*a0 + rs0; l1 = l1*a1 + rs1;
        m0 = nm0; m1 = nm1;
        __syncwarp();

        // O += P @ V  (sigma pairing: P pairs contiguous, V rows 2t,2t+1)
        #pragma unroll
        for (int kk = 0; kk < 64; kk += 8) {
            float af[4];
            float2 p0 = *(const float2*)&Ps[(wrow+grp  )*72 + kk + 2*tig];
            float2 p1 = *(const float2*)&Ps[(wrow+grp+8)*72 + kk + 2*tig];
            af[0] = p0.x; af[1] = p1.x; af[2] = p0.y; af[3] = p1.y;
            #pragma unroll
            for (int nb = 0; nb < 8; nb++) {
                float bf[2];
                bf[0] = Vs[(kk+2*tig  )*76 + nb*8 + grp];
                bf[1] = Vs[(kk+2*tig+1)*76 + nb*8 + grp];
                mma16n8k8(O[nb], af, bf);
            }
        }
        __syncwarp();
    }

    float i0 = 1.f/l0, i1 = 1.f/l1;
    int row = qt*64 + wrow + grp;
    #pragma unroll
    for (int nb = 0; nb < 8; nb++) {
        float* op = o + (size_t)(b*NT + row)*DIM + h*HD + nb*8 + 2*tig;
        *(float2*)op           = make_float2(to_tf32(O[nb][0]*i0), to_tf32(O[nb][1]*i0));
        *(float2*)(op + 8*DIM) = make_float2(to_tf32(O[nb][2]*i1), to_tf32(O[nb][3]*i1));
    }
}

// ---------------------------------------------------------------------------
// Host launcher
// ---------------------------------------------------------------------------
extern "C" void kernel_launch(void* const* d_in, const int* in_sizes, int n_in,
                              void* d_out, int out_size)
{
    const float* x       = (const float*)d_in[0];
    const float* t_emb   = (const float*)d_in[1];
    const float* norm1_g = (const float*)d_in[2];
    const float* norm1_b = (const float*)d_in[3];
    const float* Wq      = (const float*)d_in[4];
    const float* Wk      = (const float*)d_in[5];
    const float* Wv      = (const float*)d_in[6];
    const float* Wo      = (const float*)d_in[7];
    const float* norm2_g = (const float*)d_in[8];
    const float* norm2_b = (const float*)d_in[9];
    const float* W1      = (const float*)d_in[10];
    const float* W2      = (const float*)d_in[11];
    const float* ada_W   = (const float*)d_in[12];
    const float* ada_b   = (const float*)d_in[13];
    float* out = (float*)d_out;

    float *mod, *xn, *q, *k, *v, *attn, *hbuf, *wt;
    cudaGetSymbolAddress((void**)&mod,  g_mod);
    cudaGetSymbolAddress((void**)&xn,   g_xn);
    cudaGetSymbolAddress((void**)&q,    g_q);
    cudaGetSymbolAddress((void**)&k,    g_k);
    cudaGetSymbolAddress((void**)&v,    g_v);
    cudaGetSymbolAddress((void**)&attn, g_attn);
    cudaGetSymbolAddress((void**)&hbuf, g_h);
    cudaGetSymbolAddress((void**)&wt,   g_wt);

    float* wq = wt;                      // [DIM][DIM]   transposed
    float* wk = wt + 1024*1024;
    float* wv = wt + 2*1024*1024;
    float* wo = wt + 3*1024*1024;
    float* w1 = wt + 4*1024*1024;        // [MLPD][DIM]  transposed
    float* w2 = wt + 8*1024*1024;        // [DIM][MLPD]  transposed

    cudaFuncSetAttribute(gemm_qkv,
        cudaFuncAttributeMaxDynamicSharedMemorySize, G_SMEM_BYTES);
    cudaFuncSetAttribute(gemm_tc<1>,
        cudaFuncAttributeMaxDynamicSharedMemorySize, G_SMEM_BYTES);
    cudaFuncSetAttribute(gemm_tc<2>,
        cudaFuncAttributeMaxDynamicSharedMemorySize, G_SMEM_BYTES);
    cudaFuncSetAttribute(flash_tc,
        cudaFuncAttributeMaxDynamicSharedMemorySize, F_SMEM_BYTES);

    // 0. Round + transpose weights (once per launch)
    round_transpose_kernel<<<dim3(32, 32), 256>>>(Wq, wq, DIM, DIM);
    round_transpose_kernel<<<dim3(32, 32), 256>>>(Wk, wk, DIM, DIM);
    round_transpose_kernel<<<dim3(32, 32), 256>>>(Wv, wv, DIM, DIM);
    round_transpose_kernel<<<dim3(32, 32), 256>>>(Wo, wo, DIM, DIM);
    round_transpose_kernel<<<dim3(128, 32), 256>>>(W1, w1, DIM, MLPD);
    round_transpose_kernel<<<dim3(32, 128), 256>>>(W2, w2, MLPD, DIM);

    // 1. adaLN modulation
    silu_mod_kernel<<<dim3(24, BT), 256>>>(t_emb, ada_W, ada_b, mod);
    // 2. LN1 + modulate (shift=0, scale=1)
    ln_mod_kernel<<<ROWS, 256>>>(x, xn, norm1_g, norm1_b, mod, 0, 1);
    // 3. Fused QKV projections
    gemm_qkv<<<dim3(24, ROWS/128), 256, G_SMEM_BYTES>>>(xn, wq, wk, wv, q, k, v);
    // 4. RoPE
    rope_kernel<<<(BT*NT*HEADS)/256, 256>>>(q, k);
    // 5. attention
    flash_tc<<<dim3(NT/64, BT*HEADS), 128, F_SMEM_BYTES>>>(q, k, v, attn);
    // 6. out proj + gated residual (gate_msa = chunk 2) -> d_out
    gemm_tc<2><<<dim3(8, ROWS/128), 256, G_SMEM_BYTES>>>(
        attn, wo, out, ROWS, DIM, DIM, mod + 2*DIM, x);
    // 7. LN2 + modulate (shift=3, scale=4)
    ln_mod_kernel<<<ROWS, 256>>>(out, xn, norm2_g, norm2_b, mod, 3, 4);
    // 8. MLP up + exact GELU
    gemm_tc<1><<<dim3(32, ROWS/128), 256, G_SMEM_BYTES>>>(
        xn, w1, hbuf, ROWS, MLPD, DIM, nullptr, nullptr);
    // 9. MLP down + gated residual (gate_mlp = chunk 5) -> d_out
    gemm_tc<2><<<dim3(8, ROWS/128), 256, G_SMEM_BYTES>>>(
        hbuf, w2, out, ROWS, DIM, MLPD, mod + 5*DIM, out);
}